// round 15
// baseline (speedup 1.0000x reference)
#include <cuda_runtime.h>
#include <cuda_fp16.h>
#include <cstdint>

#define B_ROWS 65536
#define D_IN   784
#define D_H    1024
#define N_CLS  10
#define BN_EPS 1e-5f
#define KP     1600            // 2*784 fp16 planes + 32 zero pad
#define KREAL  1568
#define NKT    (KP / 16)       // 100 k16-tiles
#define BMT    128
#define BNT    128
#define NMT    (B_ROWS / 16)   // 4096 m16-tiles

// ---------------- device scratch ---------------------------------------------
// A in mma-fragment order: [m_tile(4096)][kt(100)][lane(32)] uint4  (200 MB)
#define XA_U4 (NMT * NKT * 32)
__device__ uint4     g_xa[XA_U4];
// B sign bytes in mma-fragment order: [strip(16)][kt(100)][half(2)][lane(32)][4B]
#define BSP_WORDS (16 * NKT * 2 * 32 * 4)         // 1.6 MB
__device__ unsigned  g_bsp[BSP_WORDS];
__device__ float     g_h[(size_t)B_ROWS * D_H];
__device__ float     g_sum[D_H];
__device__ float     g_sumsq[D_H];
__device__ unsigned  g_tbits[N_CLS][32];

// ---------------- PTX helpers -------------------------------------------------
__device__ __forceinline__ void mma16816(float* c, const uint32_t* a, const uint32_t* b) {
    asm volatile("mma.sync.aligned.m16n8k16.row.col.f32.f16.f16.f32 "
                 "{%0,%1,%2,%3}, {%4,%5,%6,%7}, {%8,%9}, {%0,%1,%2,%3};"
                 : "+f"(c[0]), "+f"(c[1]), "+f"(c[2]), "+f"(c[3])
                 : "r"(a[0]), "r"(a[1]), "r"(a[2]), "r"(a[3]), "r"(b[0]), "r"(b[1]));
}
// expand 4 sign bytes (word W) into two fp16x2 ±1 registers
#define EXPAND_B(W, r0, r1) do {                                   \
    (r0) = 0x3C003C00u ^ __byte_perm((W), 0u, 0x1404);             \
    (r1) = 0x3C003C00u ^ __byte_perm((W), 0u, 0x3424);             \
} while (0)

// pack two fp32 into hi- or lo-plane fp16x2
__device__ __forceinline__ unsigned plane_pack(float f0, float f1, int plane) {
    __half h0 = __float2half_rn(f0);
    __half h1 = __float2half_rn(f1);
    if (plane) {
        h0 = __float2half_rn(f0 - __half2float(h0));
        h1 = __float2half_rn(f1 - __half2float(h1));
    }
    __half2 p = __halves2half2(h0, h1);
    return *reinterpret_cast<unsigned*>(&p);
}

// ---------------- fused prep --------------------------------------------------
#define XA_B    ((XA_U4 + 255) / 256)                  // 51200
#define BSP_B   ((BSP_WORDS + 255) / 256)              // 1600
#define MISC_B  4                                      // covers D_H=1024 stat zeroing

__global__ void prep_all_kernel(const float* __restrict__ x,
                                const float* __restrict__ w1,
                                const float* __restrict__ w2) {
    int b = blockIdx.x;
    if (b < XA_B) {
        size_t u = (size_t)b * 256 + threadIdx.x;
        if (u >= (size_t)XA_U4) return;
        int lane = (int)(u & 31);
        int kt   = (int)((u >> 5) % NKT);
        size_t m_tile = u / (32 * NKT);
        uint4 out = make_uint4(0, 0, 0, 0);
        if (kt < 98) {                                 // kt 98,99 are zero pad
            int plane = (kt >= 49);
            int kc = kt * 16 + (lane & 3) * 2 - plane * D_IN;
            const float* xr0 = x + (m_tile * 16 + (lane >> 2)) * D_IN;
            const float* xr1 = xr0 + 8 * D_IN;
            float2 p00 = *(const float2*)(xr0 + kc);
            float2 p10 = *(const float2*)(xr1 + kc);
            float2 p01 = *(const float2*)(xr0 + kc + 8);
            float2 p11 = *(const float2*)(xr1 + kc + 8);
            out.x = plane_pack(p00.x, p00.y, plane);
            out.y = plane_pack(p10.x, p10.y, plane);
            out.z = plane_pack(p01.x, p01.y, plane);
            out.w = plane_pack(p11.x, p11.y, plane);
        }
        g_xa[u] = out;
    } else if (b < XA_B + BSP_B) {
        int widx = (b - XA_B) * 256 + threadIdx.x;
        if (widx < BSP_WORDS) {
            int wi   = widx & 3;
            int lane = (widx >> 2) & 31;
            int half = (widx >> 7) & 1;
            int skt  = widx >> 8;            // s*100 + kt
            int kt   = skt % NKT;
            int s    = skt / NKT;
            int ntile = half * 4 + wi;
            int n  = (s * 8 + ntile) * 8 + (lane >> 2);
            int kb = kt * 16 + (lane & 3) * 2;
            int kk[4] = {kb, kb + 1, kb + 8, kb + 9};
            unsigned wbits = 0;
            #pragma unroll
            for (int j = 0; j < 4; j++) {
                int k = kk[j];
                unsigned sgn = 0;
                if (k < KREAL) {
                    float v = w1[n * D_IN + (k >= D_IN ? k - D_IN : k)];
                    sgn = (v < 0.f) ? 0x80u : 0u;
                }
                wbits |= sgn << (8 * j);
            }
            g_bsp[widx] = wbits;
        }
    } else {
        int i = (b - XA_B - BSP_B) * 256 + threadIdx.x;
        if (i < D_H) { g_sum[i] = 0.f; g_sumsq[i] = 0.f; }
        if (i < N_CLS * 32) {
            int c = i >> 5, g = i & 31;
            unsigned w = 0;
            #pragma unroll
            for (int l = 0; l < 32; l++) {
                float v = w2[c * D_H + g * 32 + l];
                if (v > 0.f) w |= (1u << l);
            }
            g_tbits[c][g] = w;
        }
    }
}

// ---------------- GEMM1 + fused BN stats (all-global, barrier-free) -----------
// CTA tile 128x128, 4 warps (2x2), warp tile 64x64. A fragments and B sign
// bytes loaded straight from fragment-ordered global tables (L1/L2-resident);
// no smem, no cp.async, no __syncthreads, no ldmatrix in the mainloop.
__global__ __launch_bounds__(128, 2)
void gemm1_kernel() {
    const int tid = threadIdx.x, wid = tid >> 5, lane = tid & 31;
    const int bn = blockIdx.x, bm = blockIdx.y;
    const int warp_m = wid >> 1, warp_n = wid & 1;     // 2 x 2

    // A fragment pointers (one per m16 tile of this warp's 64-row strip)
    const uint4* Ap[4];
    #pragma unroll
    for (int mt = 0; mt < 4; mt++)
        Ap[mt] = g_xa + ((size_t)(bm * 8 + warp_m * 4 + mt) * NKT) * 32 + lane;
    // B sign base for this (bn, warp_n) strip
    const uint4* Bp = reinterpret_cast<const uint4*>(g_bsp)
                    + (size_t)(bn * 2 + warp_n) * NKT * 64 + lane;

    float acc[4][8][4];
    #pragma unroll
    for (int i = 0; i < 4; i++)
        #pragma unroll
        for (int j = 0; j < 8; j++)
            #pragma unroll
            for (int r = 0; r < 4; r++) acc[i][j][r] = 0.f;

    uint4 wa[2][4];
    uint4 wb[2][2];

    // prefetch kt = 0
    #pragma unroll
    for (int mt = 0; mt < 4; mt++) wa[0][mt] = Ap[mt][0];
    wb[0][0] = Bp[0];
    wb[0][1] = Bp[32];

    #pragma unroll 2
    for (int kt = 0; kt < NKT; kt++) {
        const int cur = kt & 1;
        if (kt + 1 < NKT) {
            const int nb = cur ^ 1;
            const size_t ka = (size_t)(kt + 1) * 32;
            #pragma unroll
            for (int mt = 0; mt < 4; mt++) wa[nb][mt] = Ap[mt][ka];
            const uint4* bk = Bp + (size_t)(kt + 1) * 64;
            wb[nb][0] = bk[0];
            wb[nb][1] = bk[32];
        }
        // expand 8 sign words -> 16 fp16x2 (+/-1) B registers
        uint32_t br[16];
        EXPAND_B(wb[cur][0].x, br[0],  br[1]);
        EXPAND_B(wb[cur][0].y, br[2],  br[3]);
        EXPAND_B(wb[cur][0].z, br[4],  br[5]);
        EXPAND_B(wb[cur][0].w, br[6],  br[7]);
        EXPAND_B(wb[cur][1].x, br[8],  br[9]);
        EXPAND_B(wb[cur][1].y, br[10], br[11]);
        EXPAND_B(wb[cur][1].z, br[12], br[13]);
        EXPAND_B(wb[cur][1].w, br[14], br[15]);
        #pragma unroll
        for (int mt = 0; mt < 4; mt++) {
            const uint32_t* af = reinterpret_cast<const uint32_t*>(&wa[cur][mt]);
            #pragma unroll
            for (int nt = 0; nt < 8; nt++)
                mma16816(acc[mt][nt], af, br + nt * 2);
        }
    }

    // ---------------- epilogue: write h + fused column stats ----------------
    float* Hb = g_h + (size_t)(bm * BMT) * D_H + bn * BNT;
    #pragma unroll
    for (int mt = 0; mt < 4; mt++) {
        int r0 = warp_m * 64 + mt * 16 + (lane >> 2);
        #pragma unroll
        for (int nt = 0; nt < 8; nt++) {
            int c = warp_n * 64 + nt * 8 + (lane & 3) * 2;
            *(float2*)(Hb + (size_t)r0 * D_H + c)       = make_float2(acc[mt][nt][0], acc[mt][nt][1]);
            *(float2*)(Hb + (size_t)(r0 + 8) * D_H + c) = make_float2(acc[mt][nt][2], acc[mt][nt][3]);
        }
    }
    #pragma unroll
    for (int nt = 0; nt < 8; nt++) {
        float s0 = 0.f, s1 = 0.f, q0 = 0.f, q1 = 0.f;
        #pragma unroll
        for (int mt = 0; mt < 4; mt++) {
            float a0 = acc[mt][nt][0], a1 = acc[mt][nt][1];
            float a2 = acc[mt][nt][2], a3 = acc[mt][nt][3];
            s0 += a0 + a2; s1 += a1 + a3;
            q0 = fmaf(a0, a0, q0); q0 = fmaf(a2, a2, q0);
            q1 = fmaf(a1, a1, q1); q1 = fmaf(a3, a3, q1);
        }
        #pragma unroll
        for (int off = 4; off < 32; off <<= 1) {
            s0 += __shfl_xor_sync(0xffffffffu, s0, off);
            s1 += __shfl_xor_sync(0xffffffffu, s1, off);
            q0 += __shfl_xor_sync(0xffffffffu, q0, off);
            q1 += __shfl_xor_sync(0xffffffffu, q1, off);
        }
        if (lane < 4) {
            int c = bn * BNT + warp_n * 64 + nt * 8 + lane * 2;
            atomicAdd(&g_sum[c],   s0);  atomicAdd(&g_sum[c + 1],   s1);
            atomicAdd(&g_sumsq[c], q0);  atomicAdd(&g_sumsq[c + 1], q1);
        }
    }
}

// ---------------- output: BN finalize + xor-popcount (high-MLP version) ------
__global__ __launch_bounds__(256)
void out_kernel(const float* __restrict__ gamma,
                const float* __restrict__ beta,
                float* __restrict__ out) {
    __shared__ float sAf[D_H];
    __shared__ float sBf[D_H];
    for (int j = threadIdx.x; j < D_H; j += 256) {
        float mu  = g_sum[j] * (1.f / B_ROWS);
        float var = g_sumsq[j] * (1.f / B_ROWS) - mu * mu;
        float inv = rsqrtf(var + BN_EPS);
        float A   = gamma[j] * inv;
        sAf[j] = A;
        sBf[j] = beta[j] - A * mu;
    }
    __syncthreads();

    int warp = (blockIdx.x * 256 + threadIdx.x) >> 5;
    int lane = threadIdx.x & 31;
    if (warp >= B_ROWS) return;

    const float* hrow = g_h + (size_t)warp * D_H;

    float v[32];
    #pragma unroll
    for (int g = 0; g < 32; g++) {
        int col = g * 32 + lane;
        v[g] = fmaf(sAf[col], hrow[col], sBf[col]);
    }

    unsigned myword = 0;
    bool anyzero = false;
    #pragma unroll
    for (int g = 0; g < 32; g++) {
        unsigned w = __ballot_sync(0xffffffffu, v[g] > 0.f);
        if (lane == g) myword = w;
        anyzero |= (v[g] == 0.f);
    }

    int adj[N_CLS];
    #pragma unroll
    for (int c = 0; c < N_CLS; c++) adj[c] = 0;
    if (__any_sync(0xffffffffu, anyzero)) {
        #pragma unroll
        for (int g = 0; g < 32; g++) {
            if (v[g] == 0.f) {
                #pragma unroll
                for (int c = 0; c < N_CLS; c++)
                    adj[c] += ((g_tbits[c][g] >> lane) & 1u) ? 1 : -1;
            }
        }
    }

    #pragma unroll
    for (int c = 0; c < N_CLS; c++) {
        unsigned x = myword ^ g_tbits[c][lane];
        int s = 32 - 2 * __popc(x) + adj[c];
        s = __reduce_add_sync(0xffffffffu, s);
        if (lane == 0) out[(size_t)warp * N_CLS + c] = (float)s;
    }
}

// ---------------- launch ------------------------------------------------------
extern "C" void kernel_launch(void* const* d_in, const int* in_sizes, int n_in,
                              void* d_out, int out_size) {
    const float* x     = (const float*)d_in[0];
    const float* w1    = (const float*)d_in[1];
    const float* gamma = (const float*)d_in[2];
    const float* beta  = (const float*)d_in[3];
    const float* w2    = (const float*)d_in[4];
    float* out = (float*)d_out;

    prep_all_kernel<<<XA_B + BSP_B + MISC_B, 256>>>(x, w1, w2);

    gemm1_kernel<<<dim3(D_H / BNT, B_ROWS / BMT), 128>>>();

    out_kernel<<<(B_ROWS * 32) / 256, 256>>>(gamma, beta, out);
}

// round 16
// speedup vs baseline: 1.2064x; 1.2064x over previous
#include <cuda_runtime.h>
#include <cuda_fp16.h>
#include <cstdint>

#define B_ROWS 65536
#define D_IN   784
#define D_H    1024
#define N_CLS  10
#define BN_EPS 1e-5f
#define KP     1664            // 2*784 fp16 planes + 96 zero pad = 13 * 128
#define KREAL  1568
#define BK     128
#define NIT    (KP / BK)       // 13
#define NKT    (KP / 16)       // 104 k16-tiles
#define BMT    128
#define BNT    128
#define SROWB  272             // A smem row stride bytes (256 data + 16 pad)
#define STAGE_B (BMT * SROWB)  // 34816 bytes (A only)
#define NSTAGE 3

// ---------------- device scratch ---------------------------------------------
__device__ __half    g_xb[(size_t)B_ROWS * KP];   // x split into 2 fp16 planes
// B sign bytes in mma-fragment order: [strip s(16)][kt(104)][half(2)][lane(32)][4B]
#define BSP_WORDS (16 * NKT * 2 * 32 * 4)         // 425984 words = 1.7 MB
__device__ unsigned  g_bsp[BSP_WORDS];
__device__ float     g_h[(size_t)B_ROWS * D_H];
__device__ float     g_sum[D_H];
__device__ float     g_sumsq[D_H];
__device__ unsigned  g_tbits[N_CLS][32];

// ---------------- PTX helpers -------------------------------------------------
__device__ __forceinline__ uint32_t s2u(const void* p) {
    uint32_t a;
    asm("{ .reg .u64 t; cvta.to.shared.u64 t, %1; cvt.u32.u64 %0, t; }" : "=r"(a) : "l"(p));
    return a;
}
__device__ __forceinline__ void cpa16(uint32_t s, const void* g) {
    asm volatile("cp.async.cg.shared.global [%0], [%1], 16;" :: "r"(s), "l"(g) : "memory");
}
__device__ __forceinline__ void cp_commit() {
    asm volatile("cp.async.commit_group;" ::: "memory");
}
__device__ __forceinline__ void ldm4(uint32_t* a, uint32_t addr) {
    asm volatile("ldmatrix.sync.aligned.m8n8.x4.shared.b16 {%0,%1,%2,%3}, [%4];"
                 : "=r"(a[0]), "=r"(a[1]), "=r"(a[2]), "=r"(a[3]) : "r"(addr));
}
__device__ __forceinline__ void mma16816(float* c, const uint32_t* a, const uint32_t* b) {
    asm volatile("mma.sync.aligned.m16n8k16.row.col.f32.f16.f16.f32 "
                 "{%0,%1,%2,%3}, {%4,%5,%6,%7}, {%8,%9}, {%0,%1,%2,%3};"
                 : "+f"(c[0]), "+f"(c[1]), "+f"(c[2]), "+f"(c[3])
                 : "r"(a[0]), "r"(a[1]), "r"(a[2]), "r"(a[3]), "r"(b[0]), "r"(b[1]));
}
// expand 4 sign bytes (word W) into two fp16x2 ±1 registers
#define EXPAND_B(W, r0, r1) do {                                   \
    (r0) = 0x3C003C00u ^ __byte_perm((W), 0u, 0x1404);             \
    (r1) = 0x3C003C00u ^ __byte_perm((W), 0u, 0x3424);             \
} while (0)

// ---------------- fused prep --------------------------------------------------
#define CONV_B  ((B_ROWS * (D_IN / 4) + 255) / 256)    // 50176
#define BSP_B   ((BSP_WORDS + 255) / 256)              // 1664
#define PAD_B   ((B_ROWS * 12 + 255) / 256)            // 3072 (96 pad cols = 12x16B/row)
#define MISC_B  4                                      // covers D_H=1024 stat zeroing

__global__ void prep_all_kernel(const float* __restrict__ x,
                                const float* __restrict__ w1,
                                const float* __restrict__ w2) {
    int b = blockIdx.x;
    if (b < CONV_B) {
        size_t i = (size_t)b * 256 + threadIdx.x;
        if (i >= (size_t)B_ROWS * (D_IN / 4)) return;
        size_t m = i / (D_IN / 4);
        int k4 = (int)(i % (D_IN / 4)) * 4;
        float4 v = *(const float4*)(x + m * D_IN + k4);
        float f[4] = {v.x, v.y, v.z, v.w};
        __half2 hi2[2], lo2[2];
        #pragma unroll
        for (int j = 0; j < 2; j++) {
            __half h0 = __float2half_rn(f[2*j]);
            __half h1 = __float2half_rn(f[2*j+1]);
            float r0 = f[2*j]   - __half2float(h0);
            float r1 = f[2*j+1] - __half2float(h1);
            hi2[j] = __halves2half2(h0, h1);
            lo2[j] = __halves2half2(__float2half_rn(r0), __float2half_rn(r1));
        }
        __half2* row = (__half2*)(g_xb + m * KP);
        int p = k4 >> 1;
        row[p]          = hi2[0];  row[p + 1]          = hi2[1];
        row[p + D_IN/2] = lo2[0];  row[p + D_IN/2 + 1] = lo2[1];
    } else if (b < CONV_B + BSP_B) {
        int widx = (b - CONV_B) * 256 + threadIdx.x;
        if (widx < BSP_WORDS) {
            int wi   = widx & 3;
            int lane = (widx >> 2) & 31;
            int half = (widx >> 7) & 1;
            int skt  = widx >> 8;            // s*104 + kt
            int kt   = skt % NKT;
            int s    = skt / NKT;
            int ntile = half * 4 + wi;
            int n  = (s * 8 + ntile) * 8 + (lane >> 2);
            int kb = kt * 16 + (lane & 3) * 2;
            int kk[4] = {kb, kb + 1, kb + 8, kb + 9};
            unsigned wbits = 0;
            #pragma unroll
            for (int j = 0; j < 4; j++) {
                int k = kk[j];
                unsigned sgn = 0;
                if (k < KREAL) {
                    float v = w1[n * D_IN + (k >= D_IN ? k - D_IN : k)];
                    sgn = (v < 0.f) ? 0x80u : 0u;
                }
                wbits |= sgn << (8 * j);
            }
            g_bsp[widx] = wbits;
        }
    } else if (b < CONV_B + BSP_B + PAD_B) {
        int i = (b - CONV_B - BSP_B) * 256 + threadIdx.x;
        if (i < B_ROWS * 12) {
            size_t row = (size_t)(i / 12);
            *(uint4*)((char*)(g_xb + row * KP + KREAL) + (i % 12) * 16) =
                make_uint4(0, 0, 0, 0);
        }
    } else {
        int i = (b - CONV_B - BSP_B - PAD_B) * 256 + threadIdx.x;
        if (i < D_H) { g_sum[i] = 0.f; g_sumsq[i] = 0.f; }
        if (i < N_CLS * 32) {
            int c = i >> 5, g = i & 31;
            unsigned w = 0;
            #pragma unroll
            for (int l = 0; l < 32; l++) {
                float v = w2[c * D_H + g * 32 + l];
                if (v > 0.f) w |= (1u << l);
            }
            g_tbits[c][g] = w;
        }
    }
}

// ---------------- GEMM1 + fused BN stats -------------------------------------
// CTA tile 128x128, 4 warps (2x2), warp tile 64x64, BK=128, 3-stage cp.async
// for A only; B synthesized from L1-resident sign bytes. 13 iterations total.
__global__ __launch_bounds__(128, 2)
void gemm1_kernel() {
    extern __shared__ char smem[];
    const uint32_t sb = s2u(smem);
    const int tid = threadIdx.x, wid = tid >> 5, lane = tid & 31;
    const int bn = blockIdx.x, bm = blockIdx.y;
    const int warp_m = wid >> 1, warp_n = wid & 1;     // 2 x 2

    const __half* Ab = g_xb + (size_t)bm * BMT * KP;
    // B sign base for this (bn, warp_n) strip; uint4 granularity
    const uint4* Bp = reinterpret_cast<const uint4*>(g_bsp)
                    + (size_t)(bn * 2 + warp_n) * NKT * 64 + lane;

    auto load_stage = [&](int it, int stage) {
        uint32_t sA = sb + stage * STAGE_B;
        int k0 = it * BK;
        #pragma unroll
        for (int j = 0; j < 16; j++) {
            int idx = tid + j * 128;                   // 2048 x 16B
            int row = idx >> 4, q = idx & 15;
            cpa16(sA + row * SROWB + q * 16,
                  (const char*)(Ab + (size_t)row * KP + k0) + q * 16);
        }
        cp_commit();
    };

    const uint32_t a_off = (warp_m * 64 + (lane & 15)) * SROWB + (lane >> 4) * 16;

    float acc[4][8][4];
    #pragma unroll
    for (int i = 0; i < 4; i++)
        #pragma unroll
        for (int j = 0; j < 8; j++)
            #pragma unroll
            for (int r = 0; r < 4; r++) acc[i][j][r] = 0.f;

    load_stage(0, 0);
    load_stage(1, 1);

    uint32_t fa[2][4][4];
    uint4 wb[2][2];

    for (int i = 0; i < NIT; i++) {
        asm volatile("cp.async.wait_group 1;" ::: "memory");
        __syncthreads();
        uint32_t sA = sb + (i - i / 3 * 3) * STAGE_B;
        const int kt0 = i * 8;

        // prefetch ks=0: A fragments from smem, B sign words from global
        #pragma unroll
        for (int mt = 0; mt < 4; mt++)
            ldm4(fa[0][mt], sA + a_off + mt * 16 * SROWB);
        wb[0][0] = Bp[(size_t)kt0 * 64];
        wb[0][1] = Bp[(size_t)kt0 * 64 + 32];

        int nxt = i + 2;
        if (nxt < NIT) load_stage(nxt, nxt - nxt / 3 * 3);
        else cp_commit();

        #pragma unroll
        for (int ks = 0; ks < 8; ks++) {
            const int cur = ks & 1;
            if (ks < 7) {
                const int nb = cur ^ 1;
                uint32_t ko = (ks + 1) * 32;
                #pragma unroll
                for (int mt = 0; mt < 4; mt++)
                    ldm4(fa[nb][mt], sA + a_off + mt * 16 * SROWB + ko);
                wb[nb][0] = Bp[(size_t)(kt0 + ks + 1) * 64];
                wb[nb][1] = Bp[(size_t)(kt0 + ks + 1) * 64 + 32];
            }
            // expand 8 sign words -> 16 fp16x2 (+/-1) B registers
            uint32_t br[16];
            EXPAND_B(wb[cur][0].x, br[0],  br[1]);
            EXPAND_B(wb[cur][0].y, br[2],  br[3]);
            EXPAND_B(wb[cur][0].z, br[4],  br[5]);
            EXPAND_B(wb[cur][0].w, br[6],  br[7]);
            EXPAND_B(wb[cur][1].x, br[8],  br[9]);
            EXPAND_B(wb[cur][1].y, br[10], br[11]);
            EXPAND_B(wb[cur][1].z, br[12], br[13]);
            EXPAND_B(wb[cur][1].w, br[14], br[15]);
            #pragma unroll
            for (int mt = 0; mt < 4; mt++)
                #pragma unroll
                for (int nt = 0; nt < 8; nt++)
                    mma16816(acc[mt][nt], fa[cur][mt], br + nt * 2);
        }
    }

    // ---------------- epilogue: write h + fused column stats ----------------
    float* Hb = g_h + (size_t)(bm * BMT) * D_H + bn * BNT;
    #pragma unroll
    for (int mt = 0; mt < 4; mt++) {
        int r0 = warp_m * 64 + mt * 16 + (lane >> 2);
        #pragma unroll
        for (int nt = 0; nt < 8; nt++) {
            int c = warp_n * 64 + nt * 8 + (lane & 3) * 2;
            *(float2*)(Hb + (size_t)r0 * D_H + c)       = make_float2(acc[mt][nt][0], acc[mt][nt][1]);
            *(float2*)(Hb + (size_t)(r0 + 8) * D_H + c) = make_float2(acc[mt][nt][2], acc[mt][nt][3]);
        }
    }
    #pragma unroll
    for (int nt = 0; nt < 8; nt++) {
        float s0 = 0.f, s1 = 0.f, q0 = 0.f, q1 = 0.f;
        #pragma unroll
        for (int mt = 0; mt < 4; mt++) {
            float a0 = acc[mt][nt][0], a1 = acc[mt][nt][1];
            float a2 = acc[mt][nt][2], a3 = acc[mt][nt][3];
            s0 += a0 + a2; s1 += a1 + a3;
            q0 = fmaf(a0, a0, q0); q0 = fmaf(a2, a2, q0);
            q1 = fmaf(a1, a1, q1); q1 = fmaf(a3, a3, q1);
        }
        #pragma unroll
        for (int off = 4; off < 32; off <<= 1) {
            s0 += __shfl_xor_sync(0xffffffffu, s0, off);
            s1 += __shfl_xor_sync(0xffffffffu, s1, off);
            q0 += __shfl_xor_sync(0xffffffffu, q0, off);
            q1 += __shfl_xor_sync(0xffffffffu, q1, off);
        }
        if (lane < 4) {
            int c = bn * BNT + warp_n * 64 + nt * 8 + lane * 2;
            atomicAdd(&g_sum[c],   s0);  atomicAdd(&g_sum[c + 1],   s1);
            atomicAdd(&g_sumsq[c], q0);  atomicAdd(&g_sumsq[c + 1], q1);
        }
    }
}

// ---------------- output: BN finalize + xor-popcount (high-MLP version) ------
__global__ __launch_bounds__(256)
void out_kernel(const float* __restrict__ gamma,
                const float* __restrict__ beta,
                float* __restrict__ out) {
    __shared__ float sAf[D_H];
    __shared__ float sBf[D_H];
    for (int j = threadIdx.x; j < D_H; j += 256) {
        float mu  = g_sum[j] * (1.f / B_ROWS);
        float var = g_sumsq[j] * (1.f / B_ROWS) - mu * mu;
        float inv = rsqrtf(var + BN_EPS);
        float A   = gamma[j] * inv;
        sAf[j] = A;
        sBf[j] = beta[j] - A * mu;
    }
    __syncthreads();

    int warp = (blockIdx.x * 256 + threadIdx.x) >> 5;
    int lane = threadIdx.x & 31;
    if (warp >= B_ROWS) return;

    const float* hrow = g_h + (size_t)warp * D_H;

    float v[32];
    #pragma unroll
    for (int g = 0; g < 32; g++) {
        int col = g * 32 + lane;
        v[g] = fmaf(sAf[col], hrow[col], sBf[col]);
    }

    unsigned myword = 0;
    bool anyzero = false;
    #pragma unroll
    for (int g = 0; g < 32; g++) {
        unsigned w = __ballot_sync(0xffffffffu, v[g] > 0.f);
        if (lane == g) myword = w;
        anyzero |= (v[g] == 0.f);
    }

    int adj[N_CLS];
    #pragma unroll
    for (int c = 0; c < N_CLS; c++) adj[c] = 0;
    if (__any_sync(0xffffffffu, anyzero)) {
        #pragma unroll
        for (int g = 0; g < 32; g++) {
            if (v[g] == 0.f) {
                #pragma unroll
                for (int c = 0; c < N_CLS; c++)
                    adj[c] += ((g_tbits[c][g] >> lane) & 1u) ? 1 : -1;
            }
        }
    }

    #pragma unroll
    for (int c = 0; c < N_CLS; c++) {
        unsigned x = myword ^ g_tbits[c][lane];
        int s = 32 - 2 * __popc(x) + adj[c];
        s = __reduce_add_sync(0xffffffffu, s);
        if (lane == 0) out[(size_t)warp * N_CLS + c] = (float)s;
    }
}

// ---------------- launch ------------------------------------------------------
extern "C" void kernel_launch(void* const* d_in, const int* in_sizes, int n_in,
                              void* d_out, int out_size) {
    const float* x     = (const float*)d_in[0];
    const float* w1    = (const float*)d_in[1];
    const float* gamma = (const float*)d_in[2];
    const float* beta  = (const float*)d_in[3];
    const float* w2    = (const float*)d_in[4];
    float* out = (float*)d_out;

    cudaFuncSetAttribute(gemm1_kernel,
                         cudaFuncAttributeMaxDynamicSharedMemorySize, NSTAGE * STAGE_B);

    prep_all_kernel<<<CONV_B + BSP_B + PAD_B + MISC_B, 256>>>(x, w1, w2);

    gemm1_kernel<<<dim3(D_H / BNT, B_ROWS / BMT), 128, NSTAGE * STAGE_B>>>();

    out_kernel<<<(B_ROWS * 32) / 256, 256>>>(gamma, beta, out);
}

// round 17
// speedup vs baseline: 1.2478x; 1.0343x over previous
#include <cuda_runtime.h>
#include <cuda_fp16.h>
#include <cstdint>

#define B_ROWS 65536
#define D_IN   784
#define D_H    1024
#define N_CLS  10
#define BN_EPS 1e-5f
#define KP     1600            // 2*784 fp16 planes + 32 zero pad = 25 * 64
#define KREAL  1568
#define BK     64
#define NIT    (KP / BK)       // 25
#define NKT    (KP / 16)       // 100 k16-tiles
#define BMT    128
#define BNT    128
#define SROWB  144             // A smem row stride bytes (128 data + 16 pad)
#define STAGE_B (BMT * SROWB)  // 18432 bytes (A only)
#define NSTAGE 4

// ---------------- device scratch ---------------------------------------------
__device__ __half    g_xb[(size_t)B_ROWS * KP];   // x split into 2 fp16 planes
// B sign bytes in mma-fragment order: [strip s(16)][kt(100)][half(2)][lane(32)][4B]
#define BSP_WORDS (16 * NKT * 2 * 32 * 4)         // 409600 words = 1.6 MB
__device__ unsigned  g_bsp[BSP_WORDS];
__device__ float     g_h[(size_t)B_ROWS * D_H];
__device__ float     g_sum[D_H];
__device__ float     g_sumsq[D_H];
__device__ unsigned  g_tbits[N_CLS][32];

// ---------------- PTX helpers -------------------------------------------------
__device__ __forceinline__ uint32_t s2u(const void* p) {
    uint32_t a;
    asm("{ .reg .u64 t; cvta.to.shared.u64 t, %1; cvt.u32.u64 %0, t; }" : "=r"(a) : "l"(p));
    return a;
}
__device__ __forceinline__ void cpa16(uint32_t s, const void* g) {
    asm volatile("cp.async.cg.shared.global [%0], [%1], 16;" :: "r"(s), "l"(g) : "memory");
}
__device__ __forceinline__ void cp_commit() {
    asm volatile("cp.async.commit_group;" ::: "memory");
}
__device__ __forceinline__ void ldm4(uint32_t* a, uint32_t addr) {
    asm volatile("ldmatrix.sync.aligned.m8n8.x4.shared.b16 {%0,%1,%2,%3}, [%4];"
                 : "=r"(a[0]), "=r"(a[1]), "=r"(a[2]), "=r"(a[3]) : "r"(addr));
}
__device__ __forceinline__ void mma16816(float* c, const uint32_t* a, const uint32_t* b) {
    asm volatile("mma.sync.aligned.m16n8k16.row.col.f32.f16.f16.f32 "
                 "{%0,%1,%2,%3}, {%4,%5,%6,%7}, {%8,%9}, {%0,%1,%2,%3};"
                 : "+f"(c[0]), "+f"(c[1]), "+f"(c[2]), "+f"(c[3])
                 : "r"(a[0]), "r"(a[1]), "r"(a[2]), "r"(a[3]), "r"(b[0]), "r"(b[1]));
}
// expand 4 sign bytes (word W) into two fp16x2 ±1 registers
#define EXPAND_B(W, r0, r1) do {                                   \
    (r0) = 0x3C003C00u ^ __byte_perm((W), 0u, 0x1404);             \
    (r1) = 0x3C003C00u ^ __byte_perm((W), 0u, 0x3424);             \
} while (0)

// ---------------- fused prep --------------------------------------------------
#define CONV_B  ((B_ROWS * (D_IN / 4) + 255) / 256)    // 50176
#define BSP_B   ((BSP_WORDS + 255) / 256)              // 1600
#define PAD_B   ((B_ROWS * 4 + 255) / 256)             // 1024
#define MISC_B  4                                      // covers D_H=1024 stat zeroing

__global__ void prep_all_kernel(const float* __restrict__ x,
                                const float* __restrict__ w1,
                                const float* __restrict__ w2) {
    int b = blockIdx.x;
    if (b < CONV_B) {
        size_t i = (size_t)b * 256 + threadIdx.x;
        if (i >= (size_t)B_ROWS * (D_IN / 4)) return;
        size_t m = i / (D_IN / 4);
        int k4 = (int)(i % (D_IN / 4)) * 4;
        float4 v = *(const float4*)(x + m * D_IN + k4);
        float f[4] = {v.x, v.y, v.z, v.w};
        __half2 hi2[2], lo2[2];
        #pragma unroll
        for (int j = 0; j < 2; j++) {
            __half h0 = __float2half_rn(f[2*j]);
            __half h1 = __float2half_rn(f[2*j+1]);
            float r0 = f[2*j]   - __half2float(h0);
            float r1 = f[2*j+1] - __half2float(h1);
            hi2[j] = __halves2half2(h0, h1);
            lo2[j] = __halves2half2(__float2half_rn(r0), __float2half_rn(r1));
        }
        __half2* row = (__half2*)(g_xb + m * KP);
        int p = k4 >> 1;
        row[p]          = hi2[0];  row[p + 1]          = hi2[1];
        row[p + D_IN/2] = lo2[0];  row[p + D_IN/2 + 1] = lo2[1];
    } else if (b < CONV_B + BSP_B) {
        int widx = (b - CONV_B) * 256 + threadIdx.x;
        if (widx < BSP_WORDS) {
            int wi   = widx & 3;
            int lane = (widx >> 2) & 31;
            int half = (widx >> 7) & 1;
            int skt  = widx >> 8;            // s*100 + kt
            int kt   = skt % NKT;
            int s    = skt / NKT;
            int ntile = half * 4 + wi;
            int n  = (s * 8 + ntile) * 8 + (lane >> 2);
            int kb = kt * 16 + (lane & 3) * 2;
            int kk[4] = {kb, kb + 1, kb + 8, kb + 9};
            unsigned wbits = 0;
            #pragma unroll
            for (int j = 0; j < 4; j++) {
                int k = kk[j];
                unsigned sgn = 0;
                if (k < KREAL) {
                    float v = w1[n * D_IN + (k >= D_IN ? k - D_IN : k)];
                    sgn = (v < 0.f) ? 0x80u : 0u;
                }
                wbits |= sgn << (8 * j);
            }
            g_bsp[widx] = wbits;
        }
    } else if (b < CONV_B + BSP_B + PAD_B) {
        int i = (b - CONV_B - BSP_B) * 256 + threadIdx.x;
        if (i < B_ROWS * 4) {
            size_t row = (size_t)(i >> 2);
            *(uint4*)((char*)(g_xb + row * KP + KREAL) + (i & 3) * 16) =
                make_uint4(0, 0, 0, 0);
        }
    } else {
        int i = (b - CONV_B - BSP_B - PAD_B) * 256 + threadIdx.x;
        if (i < D_H) { g_sum[i] = 0.f; g_sumsq[i] = 0.f; }
        if (i < N_CLS * 32) {
            int c = i >> 5, g = i & 31;
            unsigned w = 0;
            #pragma unroll
            for (int l = 0; l < 32; l++) {
                float v = w2[c * D_H + g * 32 + l];
                if (v > 0.f) w |= (1u << l);
            }
            g_tbits[c][g] = w;
        }
    }
}

// ---------------- GEMM1 + fused BN stats -------------------------------------
// CTA tile 128x128, 4 warps (2x2), warp tile 64x64, BK=64, 4-stage cp.async
// (wait_group 2) for A only; B synthesized from L1-resident sign bytes.
__global__ __launch_bounds__(128, 2)
void gemm1_kernel() {
    extern __shared__ char smem[];
    const uint32_t sb = s2u(smem);
    const int tid = threadIdx.x, wid = tid >> 5, lane = tid & 31;
    const int bn = blockIdx.x, bm = blockIdx.y;
    const int warp_m = wid >> 1, warp_n = wid & 1;     // 2 x 2

    const __half* Ab = g_xb + (size_t)bm * BMT * KP;
    // B sign base for this (bn, warp_n) strip; uint4 granularity
    const uint4* Bp = reinterpret_cast<const uint4*>(g_bsp)
                    + (size_t)(bn * 2 + warp_n) * NKT * 64 + lane;

    auto load_stage = [&](int it, int stage) {
        uint32_t sA = sb + stage * STAGE_B;
        int k0 = it * BK;
        #pragma unroll
        for (int j = 0; j < 8; j++) {
            int idx = tid + j * 128;
            int row = idx >> 3, q = idx & 7;
            cpa16(sA + row * SROWB + q * 16,
                  (const char*)(Ab + (size_t)row * KP + k0) + q * 16);
        }
        cp_commit();
    };

    const uint32_t a_off = (warp_m * 64 + (lane & 15)) * SROWB + (lane >> 4) * 16;

    float acc[4][8][4];
    #pragma unroll
    for (int i = 0; i < 4; i++)
        #pragma unroll
        for (int j = 0; j < 8; j++)
            #pragma unroll
            for (int r = 0; r < 4; r++) acc[i][j][r] = 0.f;

    load_stage(0, 0);
    load_stage(1, 1);
    load_stage(2, 2);

    uint32_t fa[2][4][4];
    uint4 wb[2][2];

    for (int i = 0; i < NIT; i++) {
        asm volatile("cp.async.wait_group 2;" ::: "memory");
        __syncthreads();
        uint32_t sA = sb + (i & 3) * STAGE_B;
        const int kt0 = i * 4;

        // prefetch ks=0: A fragments from smem, B sign words from global
        #pragma unroll
        for (int mt = 0; mt < 4; mt++)
            ldm4(fa[0][mt], sA + a_off + mt * 16 * SROWB);
        wb[0][0] = Bp[(size_t)kt0 * 64];
        wb[0][1] = Bp[(size_t)kt0 * 64 + 32];

        int nxt = i + 3;
        if (nxt < NIT) load_stage(nxt, nxt & 3);
        else cp_commit();

        #pragma unroll
        for (int ks = 0; ks < 4; ks++) {
            const int cur = ks & 1;
            if (ks < 3) {
                const int nb = cur ^ 1;
                uint32_t ko = (ks + 1) * 32;
                #pragma unroll
                for (int mt = 0; mt < 4; mt++)
                    ldm4(fa[nb][mt], sA + a_off + mt * 16 * SROWB + ko);
                wb[nb][0] = Bp[(size_t)(kt0 + ks + 1) * 64];
                wb[nb][1] = Bp[(size_t)(kt0 + ks + 1) * 64 + 32];
            }
            // expand 8 sign words -> 16 fp16x2 (+/-1) B registers
            uint32_t br[16];
            EXPAND_B(wb[cur][0].x, br[0],  br[1]);
            EXPAND_B(wb[cur][0].y, br[2],  br[3]);
            EXPAND_B(wb[cur][0].z, br[4],  br[5]);
            EXPAND_B(wb[cur][0].w, br[6],  br[7]);
            EXPAND_B(wb[cur][1].x, br[8],  br[9]);
            EXPAND_B(wb[cur][1].y, br[10], br[11]);
            EXPAND_B(wb[cur][1].z, br[12], br[13]);
            EXPAND_B(wb[cur][1].w, br[14], br[15]);
            #pragma unroll
            for (int mt = 0; mt < 4; mt++)
                #pragma unroll
                for (int nt = 0; nt < 8; nt++)
                    mma16816(acc[mt][nt], fa[cur][mt], br + nt * 2);
        }
    }

    // ---------------- epilogue: write h + fused column stats ----------------
    float* Hb = g_h + (size_t)(bm * BMT) * D_H + bn * BNT;
    #pragma unroll
    for (int mt = 0; mt < 4; mt++) {
        int r0 = warp_m * 64 + mt * 16 + (lane >> 2);
        #pragma unroll
        for (int nt = 0; nt < 8; nt++) {
            int c = warp_n * 64 + nt * 8 + (lane & 3) * 2;
            *(float2*)(Hb + (size_t)r0 * D_H + c)       = make_float2(acc[mt][nt][0], acc[mt][nt][1]);
            *(float2*)(Hb + (size_t)(r0 + 8) * D_H + c) = make_float2(acc[mt][nt][2], acc[mt][nt][3]);
        }
    }
    #pragma unroll
    for (int nt = 0; nt < 8; nt++) {
        float s0 = 0.f, s1 = 0.f, q0 = 0.f, q1 = 0.f;
        #pragma unroll
        for (int mt = 0; mt < 4; mt++) {
            float a0 = acc[mt][nt][0], a1 = acc[mt][nt][1];
            float a2 = acc[mt][nt][2], a3 = acc[mt][nt][3];
            s0 += a0 + a2; s1 += a1 + a3;
            q0 = fmaf(a0, a0, q0); q0 = fmaf(a2, a2, q0);
            q1 = fmaf(a1, a1, q1); q1 = fmaf(a3, a3, q1);
        }
        #pragma unroll
        for (int off = 4; off < 32; off <<= 1) {
            s0 += __shfl_xor_sync(0xffffffffu, s0, off);
            s1 += __shfl_xor_sync(0xffffffffu, s1, off);
            q0 += __shfl_xor_sync(0xffffffffu, q0, off);
            q1 += __shfl_xor_sync(0xffffffffu, q1, off);
        }
        if (lane < 4) {
            int c = bn * BNT + warp_n * 64 + nt * 8 + lane * 2;
            atomicAdd(&g_sum[c],   s0);  atomicAdd(&g_sum[c + 1],   s1);
            atomicAdd(&g_sumsq[c], q0);  atomicAdd(&g_sumsq[c + 1], q1);
        }
    }
}

// ---------------- output: BN finalize + xor-popcount (high-MLP version) ------
__global__ __launch_bounds__(256)
void out_kernel(const float* __restrict__ gamma,
                const float* __restrict__ beta,
                float* __restrict__ out) {
    __shared__ float sAf[D_H];
    __shared__ float sBf[D_H];
    for (int j = threadIdx.x; j < D_H; j += 256) {
        float mu  = g_sum[j] * (1.f / B_ROWS);
        float var = g_sumsq[j] * (1.f / B_ROWS) - mu * mu;
        float inv = rsqrtf(var + BN_EPS);
        float A   = gamma[j] * inv;
        sAf[j] = A;
        sBf[j] = beta[j] - A * mu;
    }
    __syncthreads();

    int warp = (blockIdx.x * 256 + threadIdx.x) >> 5;
    int lane = threadIdx.x & 31;
    if (warp >= B_ROWS) return;

    const float* hrow = g_h + (size_t)warp * D_H;

    float v[32];
    #pragma unroll
    for (int g = 0; g < 32; g++) {
        int col = g * 32 + lane;
        v[g] = fmaf(sAf[col], hrow[col], sBf[col]);
    }

    unsigned myword = 0;
    bool anyzero = false;
    #pragma unroll
    for (int g = 0; g < 32; g++) {
        unsigned w = __ballot_sync(0xffffffffu, v[g] > 0.f);
        if (lane == g) myword = w;
        anyzero |= (v[g] == 0.f);
    }

    int adj[N_CLS];
    #pragma unroll
    for (int c = 0; c < N_CLS; c++) adj[c] = 0;
    if (__any_sync(0xffffffffu, anyzero)) {
        #pragma unroll
        for (int g = 0; g < 32; g++) {
            if (v[g] == 0.f) {
                #pragma unroll
                for (int c = 0; c < N_CLS; c++)
                    adj[c] += ((g_tbits[c][g] >> lane) & 1u) ? 1 : -1;
            }
        }
    }

    #pragma unroll
    for (int c = 0; c < N_CLS; c++) {
        unsigned x = myword ^ g_tbits[c][lane];
        int s = 32 - 2 * __popc(x) + adj[c];
        s = __reduce_add_sync(0xffffffffu, s);
        if (lane == 0) out[(size_t)warp * N_CLS + c] = (float)s;
    }
}

// ---------------- launch ------------------------------------------------------
extern "C" void kernel_launch(void* const* d_in, const int* in_sizes, int n_in,
                              void* d_out, int out_size) {
    const float* x     = (const float*)d_in[0];
    const float* w1    = (const float*)d_in[1];
    const float* gamma = (const float*)d_in[2];
    const float* beta  = (const float*)d_in[3];
    const float* w2    = (const float*)d_in[4];
    float* out = (float*)d_out;

    cudaFuncSetAttribute(gemm1_kernel,
                         cudaFuncAttributeMaxDynamicSharedMemorySize, NSTAGE * STAGE_B);

    prep_all_kernel<<<CONV_B + BSP_B + PAD_B + MISC_B, 256>>>(x, w1, w2);

    gemm1_kernel<<<dim3(D_H / BNT, B_ROWS / BMT), 128, NSTAGE * STAGE_B>>>();

    out_kernel<<<(B_ROWS * 32) / 256, 256>>>(gamma, beta, out);
}